// round 6
// baseline (speedup 1.0000x reference)
#include <cuda_runtime.h>

#define Bdim  32
#define Hdim  256
#define INdim 256
#define KS    224                      // W_rec^T rows kept in shared memory
#define NLOOP 32                       // loop CTAs (one per batch)

// smem layout (bytes): Wsh 229376 | lists 2048 | hilist 256 | cnts 32 | hicnts 8
#define SM_LISTS  (KS * Hdim)          // float index where lists start
#define LOOP_SMEM (KS * Hdim * 4 + 2048 + 256 + 32 + 8 + 24)  // 231744 <= 232448

__device__ float g_Iin[(size_t)2048 * Bdim * Hdim];   // input currents (t,b,h)
__device__ float g_WT[Hdim * Hdim];                    // WT[k][h] = Wrec[h][k]
__device__ int   g_chunk_done[64];                     // tiles done per 64-step chunk

__global__ void init_kernel(const float* __restrict__ Wrec)
{
    int tid = blockIdx.x * blockDim.x + threadIdx.x;
    if (tid < 64) g_chunk_done[tid] = 0;
    for (int idx = tid; idx < Hdim * Hdim; idx += gridDim.x * blockDim.x) {
        int k = idx >> 8;
        int h = idx & 255;
        g_WT[idx] = Wrec[h * Hdim + k];
    }
}

// Compact this warp's spikes into the double-buffered index lists.
// Entries are byte offsets of W^T rows (k*1024). Warp w owns neurons [64w,64w+64);
// neurons >=224 (warp 3, lanes>=16) go to the hi list (read from g_WT via L2).
__device__ __forceinline__ void publish_list(
    bool zA, bool zB, int warp, int lane, int nb,
    unsigned* lists, unsigned* hilist, unsigned* cnts, unsigned* hicnts)
{
    unsigned mA = __ballot_sync(0xffffffffu, zA);
    unsigned mB = __ballot_sync(0xffffffffu, zB);
    unsigned mainA = (warp == 3) ? (mA & 0xFFFFu) : mA;
    unsigned mainB = (warp == 3) ? (mB & 0xFFFFu) : mB;
    unsigned lt = (1u << lane) - 1u;
    int numA = __popc(mainA);
    int posA = __popc(mainA & lt);
    int posB = numA + __popc(mainB & lt);
    unsigned* lp = lists + nb * 256 + warp * 64;
    unsigned kA = ((warp << 6) + (lane << 1)) << 10;   // row byte offset
    bool main_lane = (warp < 3) || (lane < 16);
    if (zA && main_lane) lp[posA] = kA;
    if (zB && main_lane) lp[posB] = kA + 1024;
    if (lane == 0) cnts[nb * 4 + warp] = numA + __popc(mainB);
    if (warp == 3) {
        unsigned hA = mA >> 16, hB = mB >> 16;
        int hnumA = __popc(hA);
        if (lane >= 16) {
            int sub = lane - 16;
            unsigned slt = (1u << sub) - 1u;
            int pA = __popc(hA & slt);
            int pB = hnumA + __popc(hB & slt);
            unsigned kk = (unsigned)(224 + 2 * sub) << 10;
            if (zA) hilist[nb * 32 + pA] = kk;
            if (zB) hilist[nb * 32 + pB] = kk + 1024;
        }
        if (lane == 0) hicnts[nb] = hnumA + __popc(hB);
    }
}

__device__ __forceinline__ float2 ldcg2(const void* p)
{
    float2 v;
    asm volatile("ld.global.cg.v2.f32 {%0,%1}, [%2];" : "=f"(v.x), "=f"(v.y) : "l"(p));
    return v;
}

// ---------------------------------------------------------------------------
// Fused persistent kernel. blockIdx < NLOOP: LIF recurrence (1 CTA / batch).
// blockIdx >= NLOOP: fp32 NT GEMM into g_Iin, t-major tiles, per-64-step
// chunk counters. 226KB smem forces 1 CTA/SM; grid == #SMs -> co-resident.
// ---------------------------------------------------------------------------
__global__ __launch_bounds__(256, 1) void fused_kernel(
    const float* __restrict__ x,   const float* __restrict__ z0,
    const float* __restrict__ v0,  const float* __restrict__ i0,
    const float* __restrict__ Win, float* __restrict__ out, int T)
{
    extern __shared__ float smem[];
    const int tid = threadIdx.x;

    if (blockIdx.x >= NLOOP) {
        // ================= GEMM producer =================
        float (*As)[132] = (float (*)[132])smem;
        float (*Bs)[132] = (float (*)[132])(smem + 32 * 132);
        const int g  = blockIdx.x - NLOOP;
        const int NG = gridDim.x - NLOOP;
        const int M  = T * Bdim;
        const int ntiles = (M / 128) * (Hdim / 128);
        const int tx = tid & 15;
        const int ty = tid >> 4;

        for (int tile = g; tile < ntiles; tile += NG) {
            const int m0 = (tile >> 1) * 128;
            const int n0 = (tile & 1) * 128;
            float acc[8][8];
#pragma unroll
            for (int r = 0; r < 8; ++r)
#pragma unroll
                for (int c = 0; c < 8; ++c) acc[r][c] = 0.0f;

            for (int k0 = 0; k0 < INdim; k0 += 32) {
#pragma unroll
                for (int i = 0; i < 4; ++i) {
                    int idx = tid + i * 256;
                    int row = idx >> 3;
                    int c4  = idx & 7;
                    float4 av = *(const float4*)(x + (size_t)(m0 + row) * INdim + k0 + c4 * 4);
                    As[c4 * 4 + 0][row] = av.x;
                    As[c4 * 4 + 1][row] = av.y;
                    As[c4 * 4 + 2][row] = av.z;
                    As[c4 * 4 + 3][row] = av.w;
                    float4 bv = *(const float4*)(Win + (size_t)(n0 + row) * INdim + k0 + c4 * 4);
                    Bs[c4 * 4 + 0][row] = bv.x;
                    Bs[c4 * 4 + 1][row] = bv.y;
                    Bs[c4 * 4 + 2][row] = bv.z;
                    Bs[c4 * 4 + 3][row] = bv.w;
                }
                __syncthreads();
#pragma unroll
                for (int k = 0; k < 32; ++k) {
                    float a[8], b[8];
#pragma unroll
                    for (int u = 0; u < 8; u += 4) {
                        float4 t4 = *(const float4*)&As[k][ty * 8 + u];
                        a[u] = t4.x; a[u + 1] = t4.y; a[u + 2] = t4.z; a[u + 3] = t4.w;
                        float4 s4 = *(const float4*)&Bs[k][tx * 8 + u];
                        b[u] = s4.x; b[u + 1] = s4.y; b[u + 2] = s4.z; b[u + 3] = s4.w;
                    }
#pragma unroll
                    for (int r = 0; r < 8; ++r)
#pragma unroll
                        for (int c = 0; c < 8; ++c)
                            acc[r][c] = fmaf(a[r], b[c], acc[r][c]);
                }
                __syncthreads();
            }
#pragma unroll
            for (int r = 0; r < 8; ++r)
#pragma unroll
                for (int c = 0; c < 8; c += 4) {
                    float4 o = make_float4(acc[r][c], acc[r][c + 1], acc[r][c + 2], acc[r][c + 3]);
                    *(float4*)(g_Iin + (size_t)(m0 + ty * 8 + r) * Hdim + n0 + tx * 8 + c) = o;
                }
            __threadfence();
            __syncthreads();
            if (tid == 0) atomicAdd(&g_chunk_done[m0 >> 11], 1);  // chunk = t/64
        }
        return;
    }

    // ================= LIF recurrence consumer =================
    const int b = blockIdx.x;
    float*    Wsh    = smem;                               // [KS][Hdim]
    unsigned* lists  = (unsigned*)(smem + SM_LISTS);       // [2][4][64] row offsets
    unsigned* hilist = lists + 512;                        // [2][32]
    unsigned* cnts   = hilist + 64;                        // [2][4]
    unsigned* hicnts = cnts + 8;                           // [2]

    for (int idx = tid; idx < KS * Hdim / 4; idx += 256)
        ((float4*)Wsh)[idx] = ((const float4*)g_WT)[idx];

    const bool worker = tid < 128;
    const int  j    = tid;          // worker's pair index: neurons 2j, 2j+1
    const int  warp = tid >> 5;
    const int  lane = tid & 31;

    float v0r = 0.f, v1r = 0.f, c0 = 0.f, c1 = 0.f;
    bool zA = false, zB = false;

    if (worker) {
        float2 zz = *(const float2*)(z0 + b * Hdim + 2 * j);
        float2 vv = *(const float2*)(v0 + b * Hdim + 2 * j);
        float2 ii = *(const float2*)(i0 + b * Hdim + 2 * j);
        v0r = vv.x; v1r = vv.y; c0 = ii.x; c1 = ii.y;
        publish_list(zz.x != 0.0f, zz.y != 0.0f, warp, lane, 0,
                     lists, hilist, cnts, hicnts);
    }
    if (tid == 255) {               // poll: chunk 0 must exist before prefetches
        while (*(volatile int*)&g_chunk_done[0] < 32) __nanosleep(128);
    }
    __syncthreads();

    // 2-deep input-current prefetch pipeline (L2-level loads).
    float2 f0 = make_float2(0.f, 0.f), f1 = make_float2(0.f, 0.f);
    if (worker) {
        f0 = ldcg2(g_Iin + (size_t)b * Hdim + 2 * j);
        if (T > 1) f1 = ldcg2(g_Iin + ((size_t)Bdim + b) * Hdim + 2 * j);
    }

    int pb = 0;
    for (int t = 0; t < T; ++t) {
        if (worker) {
            // (A) counts for this step's gather (list built last step).
            uint4 cc = *((const uint4*)(cnts + pb * 4));
            unsigned hc = hicnts[pb];
            if (hc > 32u) hc = 32u;                      // defensive clamp

            // (B) Early block: spike from prev-state, publish NEXT list.
            float vd0 = v0r + 0.1f * ((0.0f - v0r) + c0);
            float vd1 = v1r + 0.1f * ((0.0f - v1r) + c1);
            float id0 = c0 - 0.2f * c0;
            float id1 = c1 - 0.2f * c1;
            zA = (vd0 - 1.0f) > 0.0f;
            zB = (vd1 - 1.0f) > 0.0f;
            v0r = zA ? 0.0f : vd0;
            v1r = zB ? 0.0f : vd1;
            publish_list(zA, zB, warp, lane, pb ^ 1, lists, hilist, cnts, hicnts);

            // (C) Prefetch step t+2 input current; then store this step's spikes.
            float2 f2 = make_float2(0.f, 0.f);
            if (t + 2 < T)
                f2 = ldcg2(g_Iin + ((size_t)(t + 2) * Bdim + b) * Hdim + 2 * j);
            float2 ov;
            ov.x = zA ? 1.0f : 0.0f;
            ov.y = zB ? 1.0f : 0.0f;
            *(float2*)(out + ((size_t)t * Bdim + b) * Hdim + 2 * j) = ov;

            // (D) Hi-region (rows 224-255): <=4 predicated L2 loads, early issue.
            const char* gbase = (const char*)g_WT + (j << 3);
            float2 hw0 = {0.f, 0.f}, hw1 = {0.f, 0.f}, hw2 = {0.f, 0.f}, hw3 = {0.f, 0.f};
            if (hc > 0) hw0 = ldcg2(gbase + hilist[pb * 32 + 0]);
            if (hc > 1) hw1 = ldcg2(gbase + hilist[pb * 32 + 1]);
            if (hc > 2) hw2 = ldcg2(gbase + hilist[pb * 32 + 2]);
            if (hc > 3) hw3 = ldcg2(gbase + hilist[pb * 32 + 3]);
            float h0 = 0.f, h1 = 0.f;
            for (unsigned s = 4; s < hc; ++s) {              // rare tail
                float2 wv = ldcg2(gbase + hilist[pb * 32 + s]);
                h0 += wv.x; h1 += wv.y;
            }

            // (E) Main gather: counted loop over dense row-offset list.
            float a0 = 0.f, a1 = 0.f, a2 = 0.f, a3 = 0.f;
            const char* base = (const char*)Wsh + (j << 3);
#pragma unroll
            for (int w = 0; w < 4; ++w) {
                int n = (w == 0) ? cc.x : (w == 1) ? cc.y : (w == 2) ? cc.z : cc.w;
                if (n > 64) n = 64;                          // defensive clamp
                const unsigned* lp = lists + pb * 256 + w * 64;
                int s = 0;
                for (; s + 2 <= n; s += 2) {
                    uint2 oo = *(const uint2*)(lp + s);
                    float2 w0 = *(const float2*)(base + oo.x);
                    float2 w1 = *(const float2*)(base + oo.y);
                    a0 += w0.x; a1 += w0.y; a2 += w1.x; a3 += w1.y;
                }
                if (s < n) {
                    unsigned o = lp[s];
                    float2 wv = *(const float2*)(base + o);
                    a0 += wv.x; a1 += wv.y;
                }
            }
            h0 += (hw0.x + hw1.x) + (hw2.x + hw3.x);
            h1 += (hw0.y + hw1.y) + (hw2.y + hw3.y);

            // (F) Current update tail.
            c0 = (id0 + f0.x) + ((a0 + a2) + h0);
            c1 = (id1 + f0.y) + ((a1 + a3) + h1);

            f0 = f1;
            f1 = f2;
        } else if (tid == 255) {
            // Ensure chunk (t>>6)+1 done before workers prefetch into it.
            if ((t & 63) == 60) {
                int nc = (t >> 6) + 1;
                if (nc < (T >> 6)) {
                    while (*(volatile int*)&g_chunk_done[nc] < 32) __nanosleep(128);
                }
            }
        }
        __syncthreads();                 // publish lists; separate step t / t+1
        pb ^= 1;
    }

    if (worker) {                        // final state: [z][v][i] after spikes
        size_t base = (size_t)T * Bdim * Hdim;
        float2 zf; zf.x = zA ? 1.0f : 0.0f; zf.y = zB ? 1.0f : 0.0f;
        *(float2*)(out + base + b * Hdim + 2 * j)                   = zf;
        *(float2*)(out + base + Bdim * Hdim + b * Hdim + 2 * j)     = make_float2(v0r, v1r);
        *(float2*)(out + base + 2 * Bdim * Hdim + b * Hdim + 2 * j) = make_float2(c0, c1);
    }
}

extern "C" void kernel_launch(void* const* d_in, const int* in_sizes, int n_in,
                              void* d_out, int out_size)
{
    const float* x    = (const float*)d_in[0];   // (T,B,IN)
    const float* z0   = (const float*)d_in[1];   // (B,H)
    const float* v0   = (const float*)d_in[2];
    const float* i0   = (const float*)d_in[3];
    const float* Win  = (const float*)d_in[4];   // (H,IN)
    const float* Wrec = (const float*)d_in[5];   // (H,H)
    float* out = (float*)d_out;

    int T = in_sizes[0] / (Bdim * INdim);        // 2048

    int sms = 148;
    cudaDeviceGetAttribute(&sms, cudaDevAttrMultiProcessorCount, 0);

    cudaFuncSetAttribute(fused_kernel,
                         cudaFuncAttributeMaxDynamicSharedMemorySize, LOOP_SMEM);

    init_kernel<<<64, 256>>>(Wrec);
    fused_kernel<<<sms, 256, LOOP_SMEM>>>(x, z0, v0, i0, Win, out, T);

    (void)n_in; (void)out_size;
}

// round 9
// speedup vs baseline: 1.4612x; 1.4612x over previous
#include <cuda_runtime.h>

#define Bdim  32
#define Hdim  256
#define INdim 256
#define KS    224                      // W_rec^T rows kept in shared memory
#define KR    32                       // rows [224,256) in per-thread registers
#define NLOOP 32
#define LOOP_SMEM (KS * Hdim * 4 + 64) // 229440 <= 232448

__device__ float g_Iin[(size_t)2048 * Bdim * Hdim];   // input currents (t,b,h)
__device__ float g_WT[Hdim * Hdim];                    // WT[k][h] = Wrec[h][k]
__device__ int   g_chunk_done[64];                     // tiles done per 64-step chunk

__global__ void init_kernel(const float* __restrict__ Wrec)
{
    int tid = blockIdx.x * blockDim.x + threadIdx.x;
    if (tid < 64) g_chunk_done[tid] = 0;
    for (int idx = tid; idx < Hdim * Hdim; idx += gridDim.x * blockDim.x) {
        int k = idx >> 8;
        int h = idx & 255;
        g_WT[idx] = Wrec[h * Hdim + k];
    }
}

// ---------------------------------------------------------------------------
// Fused persistent kernel. blockIdx < NLOOP: LIF recurrence (1 CTA / batch,
// 256 threads = 1 neuron each, 8 worker warps — R1's validated config).
// blockIdx >= NLOOP: fp32 NT GEMM into g_Iin (validated R4/R6). 224KB smem
// forces 1 CTA/SM; grid == #SMs -> all CTAs co-resident, handshake safe.
// ---------------------------------------------------------------------------
__global__ __launch_bounds__(256, 1) void fused_kernel(
    const float* __restrict__ x,   const float* __restrict__ z0,
    const float* __restrict__ v0,  const float* __restrict__ i0,
    const float* __restrict__ Win, float* __restrict__ out, int T)
{
    extern __shared__ float smem[];
    const int tid = threadIdx.x;

    if (blockIdx.x >= NLOOP) {
        // ================= GEMM producer (validated) =================
        float (*As)[132] = (float (*)[132])smem;
        float (*Bs)[132] = (float (*)[132])(smem + 32 * 132);
        const int g  = blockIdx.x - NLOOP;
        const int NG = gridDim.x - NLOOP;
        const int M  = T * Bdim;
        const int ntiles = (M / 128) * (Hdim / 128);
        const int tx = tid & 15;
        const int ty = tid >> 4;

        for (int tile = g; tile < ntiles; tile += NG) {
            const int m0 = (tile >> 1) * 128;
            const int n0 = (tile & 1) * 128;
            float acc[8][8];
#pragma unroll
            for (int r = 0; r < 8; ++r)
#pragma unroll
                for (int c = 0; c < 8; ++c) acc[r][c] = 0.0f;

            for (int k0 = 0; k0 < INdim; k0 += 32) {
#pragma unroll
                for (int i = 0; i < 4; ++i) {
                    int idx = tid + i * 256;
                    int row = idx >> 3;
                    int c4  = idx & 7;
                    float4 av = *(const float4*)(x + (size_t)(m0 + row) * INdim + k0 + c4 * 4);
                    As[c4 * 4 + 0][row] = av.x;
                    As[c4 * 4 + 1][row] = av.y;
                    As[c4 * 4 + 2][row] = av.z;
                    As[c4 * 4 + 3][row] = av.w;
                    float4 bv = *(const float4*)(Win + (size_t)(n0 + row) * INdim + k0 + c4 * 4);
                    Bs[c4 * 4 + 0][row] = bv.x;
                    Bs[c4 * 4 + 1][row] = bv.y;
                    Bs[c4 * 4 + 2][row] = bv.z;
                    Bs[c4 * 4 + 3][row] = bv.w;
                }
                __syncthreads();
#pragma unroll
                for (int k = 0; k < 32; ++k) {
                    float a[8], b[8];
#pragma unroll
                    for (int u = 0; u < 8; u += 4) {
                        float4 t4 = *(const float4*)&As[k][ty * 8 + u];
                        a[u] = t4.x; a[u + 1] = t4.y; a[u + 2] = t4.z; a[u + 3] = t4.w;
                        float4 s4 = *(const float4*)&Bs[k][tx * 8 + u];
                        b[u] = s4.x; b[u + 1] = s4.y; b[u + 2] = s4.z; b[u + 3] = s4.w;
                    }
#pragma unroll
                    for (int r = 0; r < 8; ++r)
#pragma unroll
                        for (int c = 0; c < 8; ++c)
                            acc[r][c] = fmaf(a[r], b[c], acc[r][c]);
                }
                __syncthreads();
            }
#pragma unroll
            for (int r = 0; r < 8; ++r)
#pragma unroll
                for (int c = 0; c < 8; c += 4) {
                    float4 o = make_float4(acc[r][c], acc[r][c + 1], acc[r][c + 2], acc[r][c + 3]);
                    *(float4*)(g_Iin + (size_t)(m0 + ty * 8 + r) * Hdim + n0 + tx * 8 + c) = o;
                }
            __threadfence();
            __syncthreads();
            if (tid == 0) atomicAdd(&g_chunk_done[m0 >> 11], 1);  // chunk = t/64
        }
        return;
    }

    // ========= LIF recurrence consumer (R1 loop + fusion + prefetch) =========
    const int b = blockIdx.x;
    float*    Wsh   = smem;                              // [KS][Hdim]
    unsigned* masks = (unsigned*)(smem + KS * Hdim);     // [2][8] ballot masks

    // Stage W^T rows [0,KS) into smem (coalesced float4 from g_WT).
    for (int idx = tid; idx < KS * Hdim / 4; idx += 256)
        ((float4*)Wsh)[idx] = ((const float4*)g_WT)[idx];

    const int j    = tid;          // neuron index
    const int warp = tid >> 5;
    const int lane = tid & 31;

    // Rows [KS,256) for this thread's column -> registers (R1 validated).
    float wreg[KR];
#pragma unroll
    for (int r = 0; r < KR; ++r)
        wreg[r] = g_WT[(size_t)(KS + r) * Hdim + j];

    float v   = v0[b * Hdim + j];
    float cur = i0[b * Hdim + j];
    bool  z   = false;
    unsigned minit = __ballot_sync(0xffffffffu, z0[b * Hdim + j] != 0.0f);
    if (lane == 0) masks[warp] = minit;

    if (tid == 0) {                // chunk 0 must exist before first prefetches
        while (*(volatile int*)&g_chunk_done[0] < 32) __nanosleep(128);
    }
    __syncthreads();

    // 2-deep input-current prefetch pipeline (L2-level loads, validated R4).
    float f0 = __ldcg(g_Iin + (size_t)b * Hdim + j);
    float f1 = (T > 1) ? __ldcg(g_Iin + ((size_t)Bdim + b) * Hdim + j) : 0.0f;

    int pb = 0;
    for (int t = 0; t < T; ++t) {
        // Read this step's masks (published last step).
        uint4 ma = *(uint4*)&masks[pb * 8];
        uint4 mb = *(uint4*)&masks[pb * 8 + 4];
        unsigned mw[8] = {ma.x, ma.y, ma.z, ma.w, mb.x, mb.y, mb.z, mb.w};

        // LIF update early; publish NEXT masks; store spike out.
        float vd = v + 0.1f * ((0.0f - v) + cur);
        float id = cur - 0.2f * cur;
        z = (vd - 1.0f) > 0.0f;
        v = z ? 0.0f : vd;
        unsigned nm = __ballot_sync(0xffffffffu, z);
        if (lane == 0) masks[(pb ^ 1) * 8 + warp] = nm;
        out[((size_t)t * Bdim + b) * Hdim + j] = z ? 1.0f : 0.0f;

        // Prefetch t+2 input current.
        float f2 = 0.0f;
        if (t + 2 < T)
            f2 = __ldcg(g_Iin + ((size_t)(t + 2) * Bdim + b) * Hdim + j);

        // Sparse gather, words 0..6 (k<224), 2-wide unroll, dual accumulators.
        float a0 = 0.f, a1 = 0.f;
        const char* basej = (const char*)Wsh + (j << 2);
#pragma unroll
        for (int wp = 0; wp < 7; ++wp) {
            unsigned mm = mw[wp];
            const char* wpb = basej + (wp << 15);         // wp*32*1024
            while (mm) {
                int b0 = __ffs(mm) - 1;
                mm &= mm - 1;
                a0 += *(const float*)(wpb + (b0 << 10));
                if (mm) {
                    int b1 = __ffs(mm) - 1;
                    mm &= mm - 1;
                    a1 += *(const float*)(wpb + (b1 << 10));
                }
            }
        }
        // Rows [224,256): predicated register adds (R1 validated).
        unsigned m7 = mw[7];
        float h0 = 0.f, h1 = 0.f;
#pragma unroll
        for (int r = 0; r < KR; r += 2) {
            if ((m7 >> r) & 1u)       h0 += wreg[r];
            if ((m7 >> (r + 1)) & 1u) h1 += wreg[r + 1];
        }

        cur = (id + f0) + ((a0 + a1) + (h0 + h1));
        f0 = f1;
        f1 = f2;

        // chunk gate: prefetch for t'+2 first touches chunk c+1 at t'=64c+62.
        if (tid == 0 && (t & 63) == 60) {
            int nc = (t >> 6) + 1;
            if (nc < (T >> 6)) {
                while (*(volatile int*)&g_chunk_done[nc] < 32) __nanosleep(128);
            }
        }
        __syncthreads();               // publish masks; separate step t / t+1
        pb ^= 1;
    }

    // Final state: layout = [spikes (T,B,H)][z (B,H)][v (B,H)][i (B,H)]
    size_t base = (size_t)T * Bdim * Hdim;
    out[base + b * Hdim + j]                   = z ? 1.0f : 0.0f;
    out[base + Bdim * Hdim + b * Hdim + j]     = v;
    out[base + 2 * Bdim * Hdim + b * Hdim + j] = cur;
}

extern "C" void kernel_launch(void* const* d_in, const int* in_sizes, int n_in,
                              void* d_out, int out_size)
{
    const float* x    = (const float*)d_in[0];   // (T,B,IN)
    const float* z0   = (const float*)d_in[1];   // (B,H)
    const float* v0   = (const float*)d_in[2];
    const float* i0   = (const float*)d_in[3];
    const float* Win  = (const float*)d_in[4];   // (H,IN)
    const float* Wrec = (const float*)d_in[5];   // (H,H)
    float* out = (float*)d_out;

    int T = in_sizes[0] / (Bdim * INdim);        // 2048

    int sms = 148;
    cudaDeviceGetAttribute(&sms, cudaDevAttrMultiProcessorCount, 0);

    cudaFuncSetAttribute(fused_kernel,
                         cudaFuncAttributeMaxDynamicSharedMemorySize, LOOP_SMEM);

    init_kernel<<<64, 256>>>(Wrec);
    fused_kernel<<<sms, 256, LOOP_SMEM>>>(x, z0, v0, i0, Win, out, T);

    (void)n_in; (void)out_size;
}

// round 10
// speedup vs baseline: 1.5140x; 1.0361x over previous
#include <cuda_runtime.h>

#define Bdim  32
#define Hdim  256
#define INdim 256
#define KS    224                      // W_rec^T rows kept in shared memory
#define KR    32                       // rows [224,256) in helper registers
#define NLOOP 32
// smem: Wsh 229376 B | masks 64 B | hpart 2048 B
#define LOOP_SMEM (KS * Hdim * 4 + 64 + 2048)   // 231488 <= 232448

__device__ float g_Iin[(size_t)2048 * Bdim * Hdim];   // input currents (t,b,h)
__device__ float g_WT[Hdim * Hdim];                    // WT[k][h] = Wrec[h][k]
__device__ int   g_chunk_done[64];                     // tiles done per 64-step chunk

__global__ void init_kernel(const float* __restrict__ Wrec)
{
    int tid = blockIdx.x * blockDim.x + threadIdx.x;
    if (tid < 64) g_chunk_done[tid] = 0;
    for (int idx = tid; idx < Hdim * Hdim; idx += gridDim.x * blockDim.x) {
        int k = idx >> 8;
        int h = idx & 255;
        g_WT[idx] = Wrec[h * Hdim + k];
    }
}

// ---------------------------------------------------------------------------
// Fused persistent kernel, 512 threads/CTA.
// blockIdx < NLOOP: LIF recurrence. Owner warps 0-7 (tid<256): neuron state,
// LIF, ballot publish, out store, Iin prefetch, gather rows [0,128).
// Helper warps 8-15: gather rows [128,224) from smem + rows [224,256) from
// registers; partial into double-buffered hpart, folded in next step.
// blockIdx >= NLOOP: fp32 NT GEMM into g_Iin (validated; tid<256 active).
// ~226KB smem forces 1 CTA/SM; grid == #SMs -> co-resident handshake.
// ---------------------------------------------------------------------------
__global__ __launch_bounds__(512, 1) void fused_kernel(
    const float* __restrict__ x,   const float* __restrict__ z0,
    const float* __restrict__ v0,  const float* __restrict__ i0,
    const float* __restrict__ Win, float* __restrict__ out, int T)
{
    extern __shared__ float smem[];
    const int tid = threadIdx.x;

    if (blockIdx.x >= NLOOP) {
        // ================= GEMM producer (validated; tid<256 work) =========
        float (*As)[132] = (float (*)[132])smem;
        float (*Bs)[132] = (float (*)[132])(smem + 32 * 132);
        const int g  = blockIdx.x - NLOOP;
        const int NG = gridDim.x - NLOOP;
        const int M  = T * Bdim;
        const int ntiles = (M / 128) * (Hdim / 128);
        const int tx = tid & 15;
        const int ty = (tid & 255) >> 4;

        for (int tile = g; tile < ntiles; tile += NG) {
            const int m0 = (tile >> 1) * 128;
            const int n0 = (tile & 1) * 128;
            float acc[8][8];
#pragma unroll
            for (int r = 0; r < 8; ++r)
#pragma unroll
                for (int c = 0; c < 8; ++c) acc[r][c] = 0.0f;

            for (int k0 = 0; k0 < INdim; k0 += 32) {
                if (tid < 256) {
#pragma unroll
                    for (int i = 0; i < 4; ++i) {
                        int idx = tid + i * 256;
                        int row = idx >> 3;
                        int c4  = idx & 7;
                        float4 av = *(const float4*)(x + (size_t)(m0 + row) * INdim + k0 + c4 * 4);
                        As[c4 * 4 + 0][row] = av.x;
                        As[c4 * 4 + 1][row] = av.y;
                        As[c4 * 4 + 2][row] = av.z;
                        As[c4 * 4 + 3][row] = av.w;
                        float4 bv = *(const float4*)(Win + (size_t)(n0 + row) * INdim + k0 + c4 * 4);
                        Bs[c4 * 4 + 0][row] = bv.x;
                        Bs[c4 * 4 + 1][row] = bv.y;
                        Bs[c4 * 4 + 2][row] = bv.z;
                        Bs[c4 * 4 + 3][row] = bv.w;
                    }
                }
                __syncthreads();
                if (tid < 256) {
#pragma unroll
                    for (int k = 0; k < 32; ++k) {
                        float a[8], b[8];
#pragma unroll
                        for (int u = 0; u < 8; u += 4) {
                            float4 t4 = *(const float4*)&As[k][ty * 8 + u];
                            a[u] = t4.x; a[u + 1] = t4.y; a[u + 2] = t4.z; a[u + 3] = t4.w;
                            float4 s4 = *(const float4*)&Bs[k][tx * 8 + u];
                            b[u] = s4.x; b[u + 1] = s4.y; b[u + 2] = s4.z; b[u + 3] = s4.w;
                        }
#pragma unroll
                        for (int r = 0; r < 8; ++r)
#pragma unroll
                            for (int c = 0; c < 8; ++c)
                                acc[r][c] = fmaf(a[r], b[c], acc[r][c]);
                    }
                }
                __syncthreads();
            }
            if (tid < 256) {
#pragma unroll
                for (int r = 0; r < 8; ++r)
#pragma unroll
                    for (int c = 0; c < 8; c += 4) {
                        float4 o = make_float4(acc[r][c], acc[r][c + 1], acc[r][c + 2], acc[r][c + 3]);
                        *(float4*)(g_Iin + (size_t)(m0 + ty * 8 + r) * Hdim + n0 + tx * 8 + c) = o;
                    }
            }
            __threadfence();
            __syncthreads();
            if (tid == 0) atomicAdd(&g_chunk_done[m0 >> 11], 1);  // chunk = t/64
        }
        return;
    }

    // ================= LIF recurrence consumer =================
    const int b = blockIdx.x;
    float*    Wsh   = smem;                              // [KS][Hdim]
    unsigned* masks = (unsigned*)(smem + KS * Hdim);     // [2][8] ballot masks
    float*    hpart = (float*)(masks + 16);              // [2][256] helper sums

    // Stage W^T rows [0,KS) into smem (512 threads, coalesced float4).
    for (int idx = tid; idx < KS * Hdim / 4; idx += 512)
        ((float4*)Wsh)[idx] = ((const float4*)g_WT)[idx];

    const bool owner = tid < 256;
    const int  j    = tid & 255;       // neuron index
    const int  warp = tid >> 5;        // 0-7 owner, 8-15 helper
    const int  lane = tid & 31;

    float v = 0.f, cur = 0.f, f0 = 0.f, f1 = 0.f;
    float wreg[KR];
    bool  z = false;

    if (owner) {
        v   = v0[b * Hdim + j];
        cur = i0[b * Hdim + j];        // cur holds the owner-partial of i
        unsigned minit = __ballot_sync(0xffffffffu, z0[b * Hdim + j] != 0.0f);
        if (lane == 0) masks[warp] = minit;
        if (tid == 0) {                // chunk 0 ready before first prefetches
            while (*(volatile int*)&g_chunk_done[0] < 32) __nanosleep(128);
        }
    } else {
        hpart[256 + j] = 0.0f;         // buffer read at t=0 must be zero
#pragma unroll
        for (int r = 0; r < KR; ++r)   // rows [224,256) for column j
            wreg[r] = g_WT[(size_t)(KS + r) * Hdim + j];
    }
    __syncthreads();

    if (owner) {
        f0 = __ldcg(g_Iin + (size_t)b * Hdim + j);
        if (T > 1) f1 = __ldcg(g_Iin + ((size_t)Bdim + b) * Hdim + j);
    }

    int pb = 0;
    const char* basej = (const char*)Wsh + (j << 2);
    for (int t = 0; t < T; ++t) {
        if (owner) {
            // Complete last step's current with helper partial; LIF update.
            uint4 ml = *(uint4*)&masks[pb * 8];          // words 0..3
            float hp = hpart[(pb ^ 1) * 256 + j];
            float ifull = cur + hp;
            float vd = v + 0.1f * ((0.0f - v) + ifull);
            float id = ifull - 0.2f * ifull;
            z = (vd - 1.0f) > 0.0f;
            v = z ? 0.0f : vd;
            unsigned nm = __ballot_sync(0xffffffffu, z);
            if (lane == 0) masks[(pb ^ 1) * 8 + warp] = nm;
            out[((size_t)t * Bdim + b) * Hdim + j] = z ? 1.0f : 0.0f;

            // Prefetch t+2 input current.
            float f2 = 0.0f;
            if (t + 2 < T)
                f2 = __ldcg(g_Iin + ((size_t)(t + 2) * Bdim + b) * Hdim + j);

            // Gather rows [0,128): words 0..3, 2-wide, dual accumulators.
            unsigned mw[4] = {ml.x, ml.y, ml.z, ml.w};
            float a0 = 0.f, a1 = 0.f;
#pragma unroll
            for (int wp = 0; wp < 4; ++wp) {
                unsigned mm = mw[wp];
                const char* wpb = basej + (wp << 15);    // wp*32*1024
                while (mm) {
                    int b0 = __ffs(mm) - 1;
                    mm &= mm - 1;
                    a0 += *(const float*)(wpb + (b0 << 10));
                    if (mm) {
                        int b1 = __ffs(mm) - 1;
                        mm &= mm - 1;
                        a1 += *(const float*)(wpb + (b1 << 10));
                    }
                }
            }
            cur = (id + f0) + (a0 + a1);                 // owner-partial of i_t
            f0 = f1;
            f1 = f2;

            // chunk gate: prefetch for t'+2 touches chunk c+1 first at t'=64c+62.
            if (tid == 0 && (t & 63) == 60) {
                int nc = (t >> 6) + 1;
                if (nc < (T >> 6)) {
                    while (*(volatile int*)&g_chunk_done[nc] < 32) __nanosleep(128);
                }
            }
        } else {
            // Helper: gather rows [128,224) + register rows [224,256).
            uint4 mh = *(uint4*)&masks[pb * 8 + 4];      // words 4..7
            unsigned mw[3] = {mh.x, mh.y, mh.z};
            float a0 = 0.f, a1 = 0.f;
#pragma unroll
            for (int wp = 0; wp < 3; ++wp) {
                unsigned mm = mw[wp];
                const char* wpb = basej + ((wp + 4) << 15);
                while (mm) {
                    int b0 = __ffs(mm) - 1;
                    mm &= mm - 1;
                    a0 += *(const float*)(wpb + (b0 << 10));
                    if (mm) {
                        int b1 = __ffs(mm) - 1;
                        mm &= mm - 1;
                        a1 += *(const float*)(wpb + (b1 << 10));
                    }
                }
            }
            unsigned m7 = mh.w;
            float h0 = 0.f, h1 = 0.f;
#pragma unroll
            for (int r = 0; r < KR; r += 2) {
                if ((m7 >> r) & 1u)       h0 += wreg[r];
                if ((m7 >> (r + 1)) & 1u) h1 += wreg[r + 1];
            }
            hpart[pb * 256 + j] = (a0 + a1) + (h0 + h1);
        }
        __syncthreads();               // publish masks/hpart; step separation
        pb ^= 1;
    }

    if (owner) {
        // Final state: complete i with last helper partial (buffer pb^1).
        float ifin = cur + hpart[(pb ^ 1) * 256 + j];
        size_t base = (size_t)T * Bdim * Hdim;
        out[base + b * Hdim + j]                   = z ? 1.0f : 0.0f;
        out[base + Bdim * Hdim + b * Hdim + j]     = v;
        out[base + 2 * Bdim * Hdim + b * Hdim + j] = ifin;
    }
}

extern "C" void kernel_launch(void* const* d_in, const int* in_sizes, int n_in,
                              void* d_out, int out_size)
{
    const float* x    = (const float*)d_in[0];   // (T,B,IN)
    const float* z0   = (const float*)d_in[1];   // (B,H)
    const float* v0   = (const float*)d_in[2];
    const float* i0   = (const float*)d_in[3];
    const float* Win  = (const float*)d_in[4];   // (H,IN)
    const float* Wrec = (const float*)d_in[5];   // (H,H)
    float* out = (float*)d_out;

    int T = in_sizes[0] / (Bdim * INdim);        // 2048

    int sms = 148;
    cudaDeviceGetAttribute(&sms, cudaDevAttrMultiProcessorCount, 0);

    cudaFuncSetAttribute(fused_kernel,
                         cudaFuncAttributeMaxDynamicSharedMemorySize, LOOP_SMEM);

    init_kernel<<<64, 256>>>(Wrec);
    fused_kernel<<<sms, 512, LOOP_SMEM>>>(x, z0, v0, i0, Win, out, T);

    (void)n_in; (void)out_size;
}